// round 16
// baseline (speedup 1.0000x reference)
#include <cuda_runtime.h>
#include <math.h>

#define NRAYS   10000
#define NSTEPS  768
#define Zn      32
#define Yn      512
#define Xn      512
#define WPB     8                        // warps (rays) per block
#define NBLK    ((NRAYS + WPB - 1) / WPB)    // 1250

// Per-block partial sums [l1, l2, absrel]. Every block writes its slot each
// launch before any reader -> no init needed.
__device__ float    g_partials[NBLK * 3];
__device__ unsigned g_count = 0;         // reset by the last block each launch

__global__ void __launch_bounds__(WPB * 32)
ray_march_kernel(const float* __restrict__ grid,     // [5,32,512,512] (T,Z,Y,X)
                 const float* __restrict__ origin,   // [5,3]
                 const float* __restrict__ pts,      // [NRAYS,3]
                 const int*   __restrict__ tindex,   // [NRAYS]
                 float*       __restrict__ out)      // [3]
{
    const int warp = threadIdx.x >> 5;
    const int lane = threadIdx.x & 31;
    const int ray  = blockIdx.x * WPB + warp;   // grid sized exactly: always < NRAYS

    // --- per-ray setup ---
    // tindex & pts issue together; origin selected via ALU from all 5 rows
    // (15 floats, uniform, L1-resident) to avoid a dependent load.
    const int   ti  = tindex[ray];
    const float pxr = pts[ray * 3 + 0];
    const float pyr = pts[ray * 3 + 1];
    const float pzr = pts[ray * 3 + 2];

    float oxr = 0.f, oyr = 0.f, ozr = 0.f;
    #pragma unroll
    for (int k = 0; k < 5; k++) {
        const float cx = __ldg(&origin[k * 3 + 0]);
        const float cy = __ldg(&origin[k * 3 + 1]);
        const float cz = __ldg(&origin[k * 3 + 2]);
        if (k == ti) { oxr = cx; oyr = cy; ozr = cz; }
    }

    const float ox = (oxr + 51.2f) * 5.0f;
    const float oy = (oyr + 51.2f) * 5.0f;
    const float oz = (ozr + 3.2f)  * 5.0f;
    const float px = (pxr + 51.2f) * 5.0f;
    const float py = (pyr + 51.2f) * 5.0f;
    const float pz = (pzr + 3.2f)  * 5.0f;

    const float dx = px - ox, dy = py - oy, dz = pz - oz;
    const float gt = sqrtf(dx * dx + dy * dy + dz * dz);
    const float inv = 1.0f / fmaxf(gt, 1e-6f);
    const float ux = dx * inv, uy = dy * inv, uz = dz * inv;

    const float* __restrict__ slice = grid + (size_t)ti * (Zn * Yn * Xn);

    float T     = 1.0f;   // transmittance entering current chunk = exp(-cum)
    float predL = 0.0f;   // per-lane partial of sum(w * t)

    // 32 steps per iteration: lane l owns step base+l. ONE gather + ONE
    // 5-shfl scan + 2 exps per chunk. tau_stop = 12 (T < 6.1e-6):
    // expected samples/ray ~46 vs 64 with 64-wide chunks (march is
    // L1tex-wavefront bound: dur slope ~0.07us per sample/ray).
    for (int base = 0; base < NSTEPS; base += 32) {
        const float t = (float)(base + lane) + 0.5f;
        const int ix = __float2int_rd(ox + ux * t);
        const int iy = __float2int_rd(oy + uy * t);
        const int iz = __float2int_rd(oz + uz * t);
        const bool inb = ((unsigned)ix < (unsigned)Xn) &
                         ((unsigned)iy < (unsigned)Yn) &
                         ((unsigned)iz < (unsigned)Zn);
        float tau = 0.0f;
        if (inb)
            tau = fmaxf(__ldg(&slice[((iz * Yn) + iy) * Xn + ix]), 0.0f);

        // inclusive warp scan (ascending-step order)
        float cs = tau;
        #pragma unroll
        for (int off = 1; off < 32; off <<= 1) {
            float v = __shfl_up_sync(0xffffffffu, cs, off);
            if (lane >= off) cs += v;
        }

        const float E0 = __expf(-(cs - tau));    // trans entering this step
        const float E1 = __expf(-cs);            // trans leaving this step
        // OOB: tau=0 -> E0==E1 -> zero contribution (exact)
        predL += T * (E0 - E1) * t;

        T *= __shfl_sync(0xffffffffu, E1, 31);   // fold chunk's total tau

        const unsigned bal = __ballot_sync(0xffffffffu, inb);
        // Exit when: last step left the box (convex => no re-entry, all later
        // tau == 0, exact) OR T < 6.1e-6 (cum tau > 12). Typical dropped
        // tail ~2e-5 m per ray (T overshoots threshold at chunk boundary),
        // 4+ orders inside the 1e-3 rel-err budget (rel_err was 0.0 at a
        // 20x tighter threshold in R12).
        if (!((bal >> 31) & 1u) || T < 6.1e-6f) break;
    }

    // single butterfly reduction of per-lane pred partials
    #pragma unroll
    for (int off = 16; off; off >>= 1)
        predL += __shfl_xor_sync(0xffffffffu, predL, off);

    // --- per-ray loss terms ---
    const float predm = predL * 0.2f;
    const float gtm   = gt * 0.2f;          // always >= 0 -> valid, count = NRAYS
    const float diff  = gtm - predm;
    const float l1 = fabsf(diff);
    const float l2 = diff * diff * 0.5f;
    const float ar = __fdividef(fabsf(diff), fmaxf(gtm, 1e-6f));

    // Per-block reduction across WPB warps.
    __shared__ float s1[WPB], s2[WPB], s3[WPB];
    if (lane == 0) { s1[warp] = l1; s2[warp] = l2; s3[warp] = ar; }
    __syncthreads();
    if (threadIdx.x < 32) {
        float a = (lane < WPB) ? s1[lane] : 0.f;
        float b = (lane < WPB) ? s2[lane] : 0.f;
        float d = (lane < WPB) ? s3[lane] : 0.f;
        #pragma unroll
        for (int off = WPB >> 1; off; off >>= 1) {
            a += __shfl_xor_sync(0xffffffffu, a, off);
            b += __shfl_xor_sync(0xffffffffu, b, off);
            d += __shfl_xor_sync(0xffffffffu, d, off);
        }
        if (lane == 0) {
            g_partials[blockIdx.x * 3 + 0] = a;
            g_partials[blockIdx.x * 3 + 1] = b;
            g_partials[blockIdx.x * 3 + 2] = d;
        }
    }

    // --- last-block final reduction ---
    // Release atomic orders the partial stores without a gpu-scope fence
    // (avoids CCTL.IVALL chip-wide L1D flush from __threadfence).
    __shared__ unsigned s_isLast;
    __syncthreads();                     // all lane-0 stores of this block done
    if (threadIdx.x == 0) {
        unsigned old;
        asm volatile("atom.release.gpu.global.add.u32 %0, [%1], %2;"
                     : "=r"(old) : "l"(&g_count), "r"(1u) : "memory");
        s_isLast = (old == (unsigned)(NBLK - 1));
    }
    __syncthreads();

    if (s_isLast) {
        // Fixed-order strided sums: deterministic regardless of which block
        // executes this. __ldcg reads at L2 (the coherence point).
        float a = 0.f, b = 0.f, d = 0.f;
        for (int i = threadIdx.x; i < NBLK; i += WPB * 32) {
            a += __ldcg(&g_partials[i * 3 + 0]);
            b += __ldcg(&g_partials[i * 3 + 1]);
            d += __ldcg(&g_partials[i * 3 + 2]);
        }
        #pragma unroll
        for (int off = 16; off; off >>= 1) {
            a += __shfl_xor_sync(0xffffffffu, a, off);
            b += __shfl_xor_sync(0xffffffffu, b, off);
            d += __shfl_xor_sync(0xffffffffu, d, off);
        }
        if (lane == 0) { s1[warp] = a; s2[warp] = b; s3[warp] = d; }
        __syncthreads();
        if (threadIdx.x == 0) {
            float ta = 0.f, tb = 0.f, td = 0.f;
            #pragma unroll
            for (int i = 0; i < WPB; i++) { ta += s1[i]; tb += s2[i]; td += s3[i]; }
            const float cnt = (float)NRAYS;
            out[0] = ta / cnt;
            out[1] = tb / cnt;
            out[2] = td / cnt;
            g_count = 0;                 // reset for next graph replay
        }
    }
}

extern "C" void kernel_launch(void* const* d_in, const int* in_sizes, int n_in,
                              void* d_out, int out_size)
{
    const float* grid   = (const float*)d_in[0];   // (1,5,32,512,512) f32
    const float* origin = (const float*)d_in[1];   // (1,5,3) f32
    const float* pts    = (const float*)d_in[2];   // (1,10000,3) f32
    const int*   tidx   = (const int*)d_in[3];     // (1,10000) i32
    float* out = (float*)d_out;                    // 3 floats

    ray_march_kernel<<<NBLK, WPB * 32>>>(grid, origin, pts, tidx, out);
}